// round 3
// baseline (speedup 1.0000x reference)
#include <cuda_runtime.h>
#include <mma.h>
#include <math.h>

using namespace nvcuda;

#define NN   4096
#define DD   256
#define MM   4100
#define RCAP 96
#define NNZCAP 262144

// ---------------- scratch (device globals) ----------------
__device__ __align__(16) float g_deg[MM];
__device__ int   g_row_cnt[NN];
__device__ int   g_row_idx[NN * RCAP];
__device__ __align__(16) float g_row_val[NN * RCAP];
__device__ int   g_col_cnt[MM];
__device__ int   g_col_ptr[MM + 1];
__device__ int   g_col_fill[MM];
__device__ int   g_col_idx[NNZCAP];
__device__ __align__(16) float g_col_val[NNZCAP];

__device__ __align__(16) float g_Xn[NN * DD];
__device__ __align__(16) float g_En[MM * DD];
__device__ __align__(16) float g_q [NN * DD];
__device__ __align__(16) float g_k [MM * DD];
__device__ __align__(16) float g_af[NN * DD];
__device__ __align__(16) float g_X1[NN * DD];
__device__ __align__(16) float g_X2[NN * DD];
__device__ __align__(16) float g_ga[NN * DD];
__device__ __align__(16) float g_gb[NN * DD];
__device__ __align__(16) float g_A [NN];
__device__ __align__(16) float g_part[64 * DD];
__device__ __align__(16) float g_epart[4 * 32 * DD];
__device__ float g_red[2];

// ---------------- helpers ----------------
__device__ __forceinline__ float warpSum(float v) {
#pragma unroll
    for (int o = 16; o; o >>= 1) v += __shfl_xor_sync(0xffffffffu, v, o);
    return v;
}
__device__ __forceinline__ float warpMax(float v) {
#pragma unroll
    for (int o = 16; o; o >>= 1) v = fmaxf(v, __shfl_xor_sync(0xffffffffu, v, o));
    return v;
}
__device__ __forceinline__ float blockSum256(float v, float* sm) {
    int lane = threadIdx.x & 31, w = threadIdx.x >> 5;
    v = warpSum(v);
    if (lane == 0) sm[w] = v;
    __syncthreads();
    if (threadIdx.x == 0) {
        float s = 0.f;
#pragma unroll
        for (int i = 0; i < 8; i++) s += sm[i];
        sm[0] = s;
    }
    __syncthreads();
    float r = sm[0];
    __syncthreads();
    return r;
}

// ---------------- structure build ----------------
__global__ void init_k() {
    int i = blockIdx.x * blockDim.x + threadIdx.x;
    int st = gridDim.x * blockDim.x;
    for (int j = i; j < MM; j += st) { g_col_cnt[j] = 0; g_deg[j] = 0.f; }
}

__global__ void __launch_bounds__(256) build_rows(const float* __restrict__ H) {
    int warp = (blockIdx.x * blockDim.x + threadIdx.x) >> 5;
    if (warp >= NN) return;
    int lane = threadIdx.x & 31;
    const float4* row4 = (const float4*)(H + (size_t)warp * MM);  // 1025 float4
    int* ri = g_row_idx + (size_t)warp * RCAP;
    float* rv = g_row_val + (size_t)warp * RCAP;
    int base = 0;
    float4 v = row4[lane];
    for (int it = 0; it <= 32; it++) {
        float4 vn = make_float4(0.f, 0.f, 0.f, 0.f);
        if (it < 31)      vn = row4[(it + 1) * 32 + lane];
        else if (it == 31 && lane == 0) vn = row4[1024];
        int colbase = (it < 32) ? (it * 32 + lane) * 4 : 4096;
        bool valid = (it < 32) || (lane == 0);
        int c0 = valid && (v.x != 0.f), c1 = valid && (v.y != 0.f);
        int c2 = valid && (v.z != 0.f), c3 = valid && (v.w != 0.f);
        int cnt = c0 + c1 + c2 + c3;
        int inc = cnt;
#pragma unroll
        for (int o = 1; o < 32; o <<= 1) {
            int t = __shfl_up_sync(0xffffffffu, inc, o);
            if (lane >= o) inc += t;
        }
        int tot = __shfl_sync(0xffffffffu, inc, 31);
        int pos = base + inc - cnt;
        if (c0) { ri[pos] = colbase;     rv[pos] = v.x;
                  atomicAdd(&g_col_cnt[colbase], 1);     atomicAdd(&g_deg[colbase], v.x);     pos++; }
        if (c1) { ri[pos] = colbase + 1; rv[pos] = v.y;
                  atomicAdd(&g_col_cnt[colbase + 1], 1); atomicAdd(&g_deg[colbase + 1], v.y); pos++; }
        if (c2) { ri[pos] = colbase + 2; rv[pos] = v.z;
                  atomicAdd(&g_col_cnt[colbase + 2], 1); atomicAdd(&g_deg[colbase + 2], v.z); pos++; }
        if (c3) { ri[pos] = colbase + 3; rv[pos] = v.w;
                  atomicAdd(&g_col_cnt[colbase + 3], 1); atomicAdd(&g_deg[colbase + 3], v.w); pos++; }
        base += tot;
        v = vn;
    }
    if (lane == 0) g_row_cnt[warp] = base;
}

__global__ void scan_cols() {
    __shared__ int sm[1024];
    int tid = threadIdx.x;
    int b0 = tid * 5;
    int local[5];
    int s = 0;
#pragma unroll
    for (int j = 0; j < 5; j++) {
        int m = b0 + j;
        int c = (m < MM) ? g_col_cnt[m] : 0;
        local[j] = s; s += c;
    }
    sm[tid] = s;
    __syncthreads();
    for (int off = 1; off < 1024; off <<= 1) {
        int v = (tid >= off) ? sm[tid - off] : 0;
        __syncthreads();
        sm[tid] += v;
        __syncthreads();
    }
    int excl = (tid == 0) ? 0 : sm[tid - 1];
#pragma unroll
    for (int j = 0; j < 5; j++) {
        int m = b0 + j;
        if (m < MM) { g_col_ptr[m] = excl + local[j]; g_col_fill[m] = excl + local[j]; }
    }
    if (tid == 1023) g_col_ptr[MM] = sm[1023];
}

__global__ void __launch_bounds__(256) fill_cols() {
    int warp = (blockIdx.x * blockDim.x + threadIdx.x) >> 5;
    if (warp >= NN) return;
    int lane = threadIdx.x & 31;
    int cnt = g_row_cnt[warp];
    const int* ri = g_row_idx + (size_t)warp * RCAP;
    const float* rv = g_row_val + (size_t)warp * RCAP;
    for (int j = lane; j < cnt; j += 32) {
        int m = ri[j];
        float v = rv[j];
        int p = atomicAdd(&g_col_fill[m], 1);
        g_col_idx[p] = warp;
        g_col_val[p] = v;
    }
}

// ---------------- per-layer kernels ----------------
__global__ void ln_rows(const float* __restrict__ X, float* __restrict__ O,
                        const float* __restrict__ g, const float* __restrict__ b) {
    int warp = (blockIdx.x * blockDim.x + threadIdx.x) >> 5;
    if (warp >= NN) return;
    int lane = threadIdx.x & 31;
    const float4* x4 = (const float4*)(X + (size_t)warp * DD);
    float4 v0 = x4[lane], v1 = x4[lane + 32];
    float s = v0.x + v0.y + v0.z + v0.w + v1.x + v1.y + v1.z + v1.w;
    s = warpSum(s);
    float mean = s * (1.f / 256.f);
    float c0x = v0.x - mean, c0y = v0.y - mean, c0z = v0.z - mean, c0w = v0.w - mean;
    float c1x = v1.x - mean, c1y = v1.y - mean, c1z = v1.z - mean, c1w = v1.w - mean;
    float ss = c0x*c0x + c0y*c0y + c0z*c0z + c0w*c0w + c1x*c1x + c1y*c1y + c1z*c1z + c1w*c1w;
    ss = warpSum(ss);
    float rs = rsqrtf(ss * (1.f / 256.f) + 1e-5f);
    const float4* g4 = (const float4*)g;
    const float4* b4 = (const float4*)b;
    float4 G0 = g4[lane], G1 = g4[lane + 32], B0 = b4[lane], B1 = b4[lane + 32];
    float4* o4 = (float4*)(O + (size_t)warp * DD);
    o4[lane]      = make_float4(c0x*rs*G0.x + B0.x, c0y*rs*G0.y + B0.y,
                                c0z*rs*G0.z + B0.z, c0w*rs*G0.w + B0.w);
    o4[lane + 32] = make_float4(c1x*rs*G1.x + B1.x, c1y*rs*G1.y + B1.y,
                                c1z*rs*G1.z + B1.z, c1w*rs*G1.w + B1.w);
}

__global__ void __launch_bounds__(256) egather_sparse(const float* __restrict__ X,
        const float* __restrict__ g, const float* __restrict__ b) {
    int m = blockIdx.x, d = threadIdx.x;
    int p0 = g_col_ptr[m], p1 = g_col_ptr[m + 1];
    int cnt = p1 - p0;
    __shared__ int sidx[RCAP];
    __shared__ float sval[RCAP];
    __shared__ float sm[8];
    if (d < cnt && d < RCAP) { sidx[d] = g_col_idx[p0 + d]; sval[d] = g_col_val[p0 + d]; }
    __syncthreads();
    float a0 = 0.f, a1 = 0.f, a2 = 0.f, a3 = 0.f;
    int j = 0;
    for (; j + 4 <= cnt; j += 4) {
        int n0 = sidx[j], n1 = sidx[j+1], n2 = sidx[j+2], n3 = sidx[j+3];
        float x0 = X[(size_t)n0 * DD + d], x1 = X[(size_t)n1 * DD + d];
        float x2 = X[(size_t)n2 * DD + d], x3 = X[(size_t)n3 * DD + d];
        a0 = fmaf(sval[j],   x0, a0); a1 = fmaf(sval[j+1], x1, a1);
        a2 = fmaf(sval[j+2], x2, a2); a3 = fmaf(sval[j+3], x3, a3);
    }
    for (; j < cnt; j++) a0 = fmaf(sval[j], X[(size_t)sidx[j] * DD + d], a0);
    float acc = ((a0 + a1) + (a2 + a3)) / g_deg[m];
    float mean = blockSum256(acc, sm) * (1.f / 256.f);
    float c = acc - mean;
    float var = blockSum256(c * c, sm) * (1.f / 256.f);
    float rs = rsqrtf(var + 1e-5f);
    g_En[(size_t)m * DD + d] = c * rs * g[d] + b[d];
}

__global__ void __launch_bounds__(256) egather_dense_part(const float* __restrict__ X) {
    int e = blockIdx.x;          // 0..3
    int slice = blockIdx.y;      // 0..31
    int m = NN + e, d = threadIdx.x;
    int p0 = g_col_ptr[m], p1 = g_col_ptr[m + 1];
    int cnt = p1 - p0;
    int per = (cnt + 31) / 32;
    int s0 = p0 + slice * per;
    int s1 = min(s0 + per, p1);
    float a0 = 0.f, a1 = 0.f, a2 = 0.f, a3 = 0.f;
    int p = s0;
    for (; p + 4 <= s1; p += 4) {
        int n0 = g_col_idx[p], n1 = g_col_idx[p+1], n2 = g_col_idx[p+2], n3 = g_col_idx[p+3];
        float w0 = g_col_val[p], w1 = g_col_val[p+1], w2 = g_col_val[p+2], w3 = g_col_val[p+3];
        a0 = fmaf(w0, X[(size_t)n0 * DD + d], a0);
        a1 = fmaf(w1, X[(size_t)n1 * DD + d], a1);
        a2 = fmaf(w2, X[(size_t)n2 * DD + d], a2);
        a3 = fmaf(w3, X[(size_t)n3 * DD + d], a3);
    }
    for (; p < s1; p++) a0 = fmaf(g_col_val[p], X[(size_t)g_col_idx[p] * DD + d], a0);
    g_epart[(size_t)(e * 32 + slice) * DD + d] = (a0 + a1) + (a2 + a3);
}

__global__ void __launch_bounds__(256) egather_dense_fin(const float* __restrict__ g,
                                                          const float* __restrict__ b) {
    int e = blockIdx.x, d = threadIdx.x;
    float acc = 0.f;
#pragma unroll
    for (int s = 0; s < 32; s++) acc += g_epart[(size_t)(e * 32 + s) * DD + d];
    acc /= g_deg[NN + e];
    __shared__ float sm[8];
    float mean = blockSum256(acc, sm) * (1.f / 256.f);
    float c = acc - mean;
    float var = blockSum256(c * c, sm) * (1.f / 256.f);
    float rs = rsqrtf(var + 1e-5f);
    g_En[(size_t)(NN + e) * DD + d] = c * rs * g[d] + b[d];
}

// ---------------- tf32 tensor-core GEMM ----------------
// C[rows,256] = A[rows,256] @ W[256,256]^T + bias, fused epilogue.
// Block: 256 threads = 8 warps (4 row-groups x 2 col-groups), 128x64 tile.
__device__ __forceinline__ void gemm_tc_body(const float* __restrict__ A,
        const float* __restrict__ W, const float* __restrict__ bias,
        float* __restrict__ C, const float* __restrict__ R, int epi) {
    __shared__ __align__(16) float smC[128 * 64];
    int tid = threadIdx.x;
    int wid = tid >> 5;
    int wr = wid >> 1;      // 0..3
    int wc = wid & 1;       // 0..1
    int rowBase = blockIdx.x * 128;
    int colBase = blockIdx.y * 64;

    wmma::fragment<wmma::accumulator, 16, 16, 8, float> acc[2][2];
#pragma unroll
    for (int i = 0; i < 2; i++)
#pragma unroll
        for (int j = 0; j < 2; j++) wmma::fill_fragment(acc[i][j], 0.f);

    const float* Abase = A + (size_t)(rowBase + wr * 32) * DD;
    const float* Wbase = W + (size_t)(colBase + wc * 32) * DD;

#pragma unroll 4
    for (int k0 = 0; k0 < 256; k0 += 8) {
        wmma::fragment<wmma::matrix_a, 16, 16, 8, wmma::precision::tf32, wmma::row_major> a[2];
        wmma::fragment<wmma::matrix_b, 16, 16, 8, wmma::precision::tf32, wmma::col_major> b[2];
        wmma::load_matrix_sync(a[0], Abase + k0, DD);
        wmma::load_matrix_sync(a[1], Abase + 16 * DD + k0, DD);
        wmma::load_matrix_sync(b[0], Wbase + k0, DD);
        wmma::load_matrix_sync(b[1], Wbase + 16 * DD + k0, DD);
#pragma unroll
        for (int t = 0; t < a[0].num_elements; t++) {
            a[0].x[t] = wmma::__float_to_tf32(a[0].x[t]);
            a[1].x[t] = wmma::__float_to_tf32(a[1].x[t]);
        }
#pragma unroll
        for (int t = 0; t < b[0].num_elements; t++) {
            b[0].x[t] = wmma::__float_to_tf32(b[0].x[t]);
            b[1].x[t] = wmma::__float_to_tf32(b[1].x[t]);
        }
#pragma unroll
        for (int i = 0; i < 2; i++)
#pragma unroll
            for (int j = 0; j < 2; j++)
                wmma::mma_sync(acc[i][j], a[i], b[j], acc[i][j]);
    }
#pragma unroll
    for (int i = 0; i < 2; i++)
#pragma unroll
        for (int j = 0; j < 2; j++)
            wmma::store_matrix_sync(&smC[(wr * 32 + i * 16) * 64 + wc * 32 + j * 16],
                                    acc[i][j], 64, wmma::mem_row_major);
    __syncthreads();

    // epilogue: 8192 elems / 256 threads = 8 float4 per thread
#pragma unroll
    for (int e4 = 0; e4 < 8; e4++) {
        int idx = (tid + e4 * 256) * 4;
        int row = idx >> 6;
        int col = idx & 63;
        float4 v = *(float4*)&smC[idx];
        float4 bv = *(const float4*)(bias + colBase + col);
        v.x += bv.x; v.y += bv.y; v.z += bv.z; v.w += bv.w;
        int grow = rowBase + row;
        if (epi == 1) {
            float4 rv = *(const float4*)(R + (size_t)grow * DD + colBase + col);
            v.x = fmaxf(v.x, 0.f) * 0.5f + 0.5f * rv.x;
            v.y = fmaxf(v.y, 0.f) * 0.5f + 0.5f * rv.y;
            v.z = fmaxf(v.z, 0.f) * 0.5f + 0.5f * rv.z;
            v.w = fmaxf(v.w, 0.f) * 0.5f + 0.5f * rv.w;
        } else if (epi == 2) {
            v.x = tanhf(v.x); v.y = tanhf(v.y); v.z = tanhf(v.z); v.w = tanhf(v.w);
        } else if (epi == 3) {
            v.x = 1.f / (1.f + __expf(-v.x)); v.y = 1.f / (1.f + __expf(-v.y));
            v.z = 1.f / (1.f + __expf(-v.z)); v.w = 1.f / (1.f + __expf(-v.w));
        }
        *(float4*)(C + (size_t)grow * DD + colBase + col) = v;
    }
}

template <int EPI>
__global__ void __launch_bounds__(256) gemm_tc(const float* __restrict__ A,
        const float* __restrict__ W, const float* __restrict__ bias,
        float* __restrict__ C, const float* __restrict__ R) {
    gemm_tc_body(A, W, bias, C, R, EPI);
}

template <int EPI0, int EPI1>
__global__ void __launch_bounds__(256) gemm_tc_dual(
        const float* __restrict__ A0, const float* __restrict__ W0,
        const float* __restrict__ b0, float* __restrict__ C0,
        const float* __restrict__ A1, const float* __restrict__ W1,
        const float* __restrict__ b1, float* __restrict__ C1) {
    if (blockIdx.z == 0) gemm_tc_body(A0, W0, b0, C0, nullptr, EPI0);
    else                 gemm_tc_body(A1, W1, b1, C1, nullptr, EPI1);
}

__global__ void ktail(const float* __restrict__ Wkt, const float* __restrict__ bkt,
                      const float* __restrict__ Wks, const float* __restrict__ bks) {
    __shared__ __align__(16) float e[4][DD];
    int tid = threadIdx.x;
#pragma unroll
    for (int r = 0; r < 4; r++) e[r][tid] = g_En[(size_t)(NN + r) * DD + tid];
    __syncthreads();
    int h = tid >> 5, lane = tid & 31;
    for (int t = h; t < 4 * DD; t += 8) {
        int r = t >> 8, o = t & 255;
        const float* w = ((r < 3) ? Wkt : Wks) + (size_t)o * DD;
        const float4* w4 = (const float4*)w;
        const float4* e4 = (const float4*)e[r];
        float4 a = w4[lane], b = e4[lane];
        float acc = a.x*b.x + a.y*b.y + a.z*b.z + a.w*b.w;
        float4 a2 = w4[lane + 32], b2 = e4[lane + 32];
        acc += a2.x*b2.x + a2.y*b2.y + a2.z*b2.z + a2.w*b2.w;
        acc = warpSum(acc);
        if (lane == 0) g_k[(size_t)(NN + r) * DD + o] = acc + ((r < 3) ? bkt[o] : bks[o]);
    }
}

// sparse masked MHA, single pass online softmax; block per node, warp per head.
__global__ void __launch_bounds__(256) attn_k() {
    int n = blockIdx.x;
    int tid = threadIdx.x;
    int h = tid >> 5, lane = tid & 31;
    __shared__ int sidx[RCAP];
    int cnt = g_row_cnt[n];
    if (tid < cnt) sidx[tid] = g_row_idx[(size_t)n * RCAP + tid];
    __syncthreads();
    int off = h * 32 + lane;
    float qv = g_q[(size_t)n * DD + off];
    float m = -1e30f, s = 0.f, acc = 0.f;
    const float sc = 0.17677669529663687f;  // 1/sqrt(32)
    for (int j0 = 0; j0 < cnt; j0 += 4) {
        int c = cnt - j0;
        float kv0 = g_k[(size_t)sidx[j0] * DD + off];
        float kv1 = (c > 1) ? g_k[(size_t)sidx[j0+1] * DD + off] : 0.f;
        float kv2 = (c > 2) ? g_k[(size_t)sidx[j0+2] * DD + off] : 0.f;
        float kv3 = (c > 3) ? g_k[(size_t)sidx[j0+3] * DD + off] : 0.f;
        float p0 = qv * kv0, p1 = qv * kv1, p2 = qv * kv2, p3 = qv * kv3;
#pragma unroll
        for (int o = 16; o; o >>= 1) {
            p0 += __shfl_xor_sync(0xffffffffu, p0, o);
            p1 += __shfl_xor_sync(0xffffffffu, p1, o);
            p2 += __shfl_xor_sync(0xffffffffu, p2, o);
            p3 += __shfl_xor_sync(0xffffffffu, p3, o);
        }
        p0 *= sc; p1 *= sc; p2 *= sc; p3 *= sc;
        {
            if (p0 > m) { float r = __expf(m - p0); s *= r; acc *= r; m = p0; }
            float e = __expf(p0 - m); s += e; acc = fmaf(e, kv0, acc);
        }
        if (c > 1) {
            if (p1 > m) { float r = __expf(m - p1); s *= r; acc *= r; m = p1; }
            float e = __expf(p1 - m); s += e; acc = fmaf(e, kv1, acc);
        }
        if (c > 2) {
            if (p2 > m) { float r = __expf(m - p2); s *= r; acc *= r; m = p2; }
            float e = __expf(p2 - m); s += e; acc = fmaf(e, kv2, acc);
        }
        if (c > 3) {
            if (p3 > m) { float r = __expf(m - p3); s *= r; acc *= r; m = p3; }
            float e = __expf(p3 - m); s += e; acc = fmaf(e, kv3, acc);
        }
    }
    g_af[(size_t)n * DD + off] = acc / s;
}

// ---------------- pooling head ----------------
__global__ void gated_score(const float* __restrict__ cw, const float* __restrict__ cb) {
    int warp = (blockIdx.x * blockDim.x + threadIdx.x) >> 5;
    if (warp >= NN) return;
    int lane = threadIdx.x & 31;
    const float4* a4 = (const float4*)(g_ga + (size_t)warp * DD);
    const float4* b4 = (const float4*)(g_gb + (size_t)warp * DD);
    const float4* c4 = (const float4*)cw;
    float acc = 0.f;
#pragma unroll
    for (int t = 0; t < 2; t++) {
        float4 a = a4[lane + t * 32], b = b4[lane + t * 32], c = c4[lane + t * 32];
        acc += a.x*b.x*c.x + a.y*b.y*c.y + a.z*b.z*c.z + a.w*b.w*c.w;
    }
    acc = warpSum(acc);
    if (lane == 0) g_A[warp] = acc + cb[0];
}

__global__ void softmax_stats() {
    __shared__ float sm[32];
    int tid = threadIdx.x, lane = tid & 31, w = tid >> 5;
    float mx = -1e30f;
    for (int i = tid; i < NN; i += 1024) mx = fmaxf(mx, g_A[i]);
    mx = warpMax(mx);
    if (lane == 0) sm[w] = mx;
    __syncthreads();
    if (w == 0) { float v = sm[lane]; v = warpMax(v); if (lane == 0) sm[0] = v; }
    __syncthreads();
    mx = sm[0];
    __syncthreads();
    float s = 0.f;
    for (int i = tid; i < NN; i += 1024) s += __expf(g_A[i] - mx);
    s = warpSum(s);
    if (lane == 0) sm[w] = s;
    __syncthreads();
    if (tid == 0) {
        float t = 0.f;
        for (int i = 0; i < 32; i++) t += sm[i];
        g_red[0] = mx; g_red[1] = t;
    }
}

__global__ void pool_partial(const float* __restrict__ F) {
    int d = threadIdx.x, b = blockIdx.x;
    float mx = g_red[0];
    float acc = 0.f;
    int n0 = b * 64;
    for (int j = 0; j < 64; j++) {
        float wgt = __expf(g_A[n0 + j] - mx);
        acc = fmaf(wgt, F[(size_t)(n0 + j) * DD + d], acc);
    }
    g_part[b * DD + d] = acc;
}

__global__ void final_out(const float* __restrict__ ow, const float* __restrict__ ob,
                          float* __restrict__ out) {
    __shared__ float pooled[DD];
    int d = threadIdx.x;
    float acc = 0.f;
    for (int b = 0; b < 64; b++) acc += g_part[b * DD + d];
    pooled[d] = acc / g_red[1];
    __syncthreads();
    int h = d >> 5, lane = d & 31;
    if (h < 4) {
        const float* w = ow + (size_t)h * DD;
        float a = 0.f;
        for (int k = lane; k < DD; k += 32) a = fmaf(pooled[k], w[k], a);
        a = warpSum(a);
        if (lane == 0) out[h] = a + ob[h];
    }
}

// ---------------- host orchestration ----------------
struct DevPtrs {
    float *Xn, *En, *q, *k, *af, *X1, *X2, *ga, *gb;
};

static DevPtrs get_ptrs() {
    static DevPtrs p = {};
    static bool init = false;
    if (!init) {
        cudaGetSymbolAddress((void**)&p.Xn, g_Xn);
        cudaGetSymbolAddress((void**)&p.En, g_En);
        cudaGetSymbolAddress((void**)&p.q,  g_q);
        cudaGetSymbolAddress((void**)&p.k,  g_k);
        cudaGetSymbolAddress((void**)&p.af, g_af);
        cudaGetSymbolAddress((void**)&p.X1, g_X1);
        cudaGetSymbolAddress((void**)&p.X2, g_X2);
        cudaGetSymbolAddress((void**)&p.ga, g_ga);
        cudaGetSymbolAddress((void**)&p.gb, g_gb);
        init = true;
    }
    return p;
}

static void run_layer(const DevPtrs& p, const float* Xin, float* Xout, int l,
                      const float* Wq_w, const float* Wq_b,
                      const float* Wkn_w, const float* Wkn_b,
                      const float* Wkt_w, const float* Wkt_b,
                      const float* Wks_w, const float* Wks_b,
                      const float* fc_w, const float* fc_b,
                      const float* ln_g, const float* ln_b) {
    const int WOFF = DD * DD;
    ln_rows<<<512, 256>>>(Xin, p.Xn, ln_g + l * DD, ln_b + l * DD);
    egather_sparse<<<NN, 256>>>(Xin, ln_g + l * DD, ln_b + l * DD);
    egather_dense_part<<<dim3(4, 32), 256>>>(Xin);
    egather_dense_fin<<<4, 256>>>(ln_g + l * DD, ln_b + l * DD);
    dim3 grid2(32, 4, 2);
    gemm_tc_dual<0, 0><<<grid2, 256>>>(p.Xn, Wq_w + l * WOFF, Wq_b + l * DD, p.q,
                                       p.En, Wkn_w + l * WOFF, Wkn_b + l * DD, p.k);
    ktail<<<1, 256>>>(Wkt_w + l * WOFF, Wkt_b + l * DD, Wks_w + l * WOFF, Wks_b + l * DD);
    attn_k<<<NN, 256>>>();
    dim3 grid(32, 4);
    gemm_tc<1><<<grid, 256>>>(p.af, fc_w + l * WOFF, fc_b + l * DD, Xout, Xin);
}

extern "C" void kernel_launch(void* const* d_in, const int* in_sizes, int n_in,
                              void* d_out, int out_size) {
    (void)in_sizes; (void)n_in; (void)out_size;
    const float* X     = (const float*)d_in[0];
    const float* H     = (const float*)d_in[1];
    const float* Wq_w  = (const float*)d_in[2];
    const float* Wq_b  = (const float*)d_in[3];
    const float* Wkn_w = (const float*)d_in[4];
    const float* Wkn_b = (const float*)d_in[5];
    const float* Wkt_w = (const float*)d_in[6];
    const float* Wkt_b = (const float*)d_in[7];
    const float* Wks_w = (const float*)d_in[8];
    const float* Wks_b = (const float*)d_in[9];
    const float* fc_w  = (const float*)d_in[10];
    const float* fc_b  = (const float*)d_in[11];
    const float* ln_g  = (const float*)d_in[12];
    const float* ln_b  = (const float*)d_in[13];
    const float* aw    = (const float*)d_in[14];
    const float* ab    = (const float*)d_in[15];
    const float* bw    = (const float*)d_in[16];
    const float* bb    = (const float*)d_in[17];
    const float* cw    = (const float*)d_in[18];
    const float* cb    = (const float*)d_in[19];
    const float* out_w = (const float*)d_in[20];
    const float* out_b = (const float*)d_in[21];
    float* out = (float*)d_out;

    DevPtrs p = get_ptrs();

    // structure build from H (single pass over H)
    init_k<<<32, 256>>>();
    build_rows<<<512, 256>>>(H);
    scan_cols<<<1, 1024>>>();
    fill_cols<<<512, 256>>>();

    // two HetHyper layers
    run_layer(p, X,    p.X1, 0, Wq_w, Wq_b, Wkn_w, Wkn_b, Wkt_w, Wkt_b,
              Wks_w, Wks_b, fc_w, fc_b, ln_g, ln_b);
    run_layer(p, p.X1, p.X2, 1, Wq_w, Wq_b, Wkn_w, Wkn_b, Wkt_w, Wkt_b,
              Wks_w, Wks_b, fc_w, fc_b, ln_g, ln_b);

    // gated attention pooling + classifier
    dim3 grid2(32, 4, 2);
    gemm_tc_dual<2, 3><<<grid2, 256>>>(p.X2, aw, ab, p.ga, p.X2, bw, bb, p.gb);
    gated_score<<<512, 256>>>(cw, cb);
    softmax_stats<<<1, 1024>>>();
    pool_partial<<<64, 256>>>(p.X2);
    final_out<<<1, 256>>>(out_w, out_b, out);
}

// round 4
// speedup vs baseline: 1.6460x; 1.6460x over previous
#include <cuda_runtime.h>
#include <mma.h>
#include <math.h>

using namespace nvcuda;

#define NN   4096
#define DD   256
#define MM   4100
#define RCAP 96
#define NNZCAP 262144

// ---------------- scratch (device globals) ----------------
__device__ __align__(16) float g_deg[MM];
__device__ int   g_row_cnt[NN];
__device__ int   g_row_idx[NN * RCAP];
__device__ __align__(16) float g_row_val[NN * RCAP];
__device__ int   g_col_cnt[MM];
__device__ int   g_col_ptr[MM + 1];
__device__ int   g_col_fill[MM];
__device__ int   g_col_idx[NNZCAP];
__device__ __align__(16) float g_col_val[NNZCAP];

__device__ __align__(16) float g_Xn[NN * DD];
__device__ __align__(16) float g_En[MM * DD];
__device__ __align__(16) float g_q [NN * DD];
__device__ __align__(16) float g_k [MM * DD];
__device__ __align__(16) float g_af[NN * DD];
__device__ __align__(16) float g_X1[NN * DD];
__device__ __align__(16) float g_X2[NN * DD];
__device__ __align__(16) float g_ga[NN * DD];
__device__ __align__(16) float g_gb[NN * DD];
__device__ __align__(16) float g_A [NN];
__device__ __align__(16) float g_part[64 * DD];
__device__ __align__(16) float g_epart[4 * 32 * DD];
__device__ float g_red[2];

// ---------------- helpers ----------------
__device__ __forceinline__ float warpSum(float v) {
#pragma unroll
    for (int o = 16; o; o >>= 1) v += __shfl_xor_sync(0xffffffffu, v, o);
    return v;
}
__device__ __forceinline__ float warpMax(float v) {
#pragma unroll
    for (int o = 16; o; o >>= 1) v = fmaxf(v, __shfl_xor_sync(0xffffffffu, v, o));
    return v;
}
__device__ __forceinline__ float blockSum256(float v, float* sm) {
    int lane = threadIdx.x & 31, w = threadIdx.x >> 5;
    v = warpSum(v);
    if (lane == 0) sm[w] = v;
    __syncthreads();
    if (threadIdx.x == 0) {
        float s = 0.f;
#pragma unroll
        for (int i = 0; i < 8; i++) s += sm[i];
        sm[0] = s;
    }
    __syncthreads();
    float r = sm[0];
    __syncthreads();
    return r;
}

// ---------------- structure build ----------------
__global__ void init_k() {
    int i = blockIdx.x * blockDim.x + threadIdx.x;
    int st = gridDim.x * blockDim.x;
    for (int j = i; j < MM; j += st) { g_col_cnt[j] = 0; g_deg[j] = 0.f; }
}

__global__ void __launch_bounds__(256) build_rows(const float* __restrict__ H) {
    int warp = (blockIdx.x * blockDim.x + threadIdx.x) >> 5;
    if (warp >= NN) return;
    int lane = threadIdx.x & 31;
    const float4* row4 = (const float4*)(H + (size_t)warp * MM);  // 1025 float4
    int* ri = g_row_idx + (size_t)warp * RCAP;
    float* rv = g_row_val + (size_t)warp * RCAP;
    int base = 0;
    float4 v = row4[lane];
    for (int it = 0; it <= 32; it++) {
        float4 vn = make_float4(0.f, 0.f, 0.f, 0.f);
        if (it < 31)      vn = row4[(it + 1) * 32 + lane];
        else if (it == 31 && lane == 0) vn = row4[1024];
        int colbase = (it < 32) ? (it * 32 + lane) * 4 : 4096;
        bool valid = (it < 32) || (lane == 0);
        int c0 = valid && (v.x != 0.f), c1 = valid && (v.y != 0.f);
        int c2 = valid && (v.z != 0.f), c3 = valid && (v.w != 0.f);
        int cnt = c0 + c1 + c2 + c3;
        int inc = cnt;
#pragma unroll
        for (int o = 1; o < 32; o <<= 1) {
            int t = __shfl_up_sync(0xffffffffu, inc, o);
            if (lane >= o) inc += t;
        }
        int tot = __shfl_sync(0xffffffffu, inc, 31);
        int pos = base + inc - cnt;
        if (c0) { ri[pos] = colbase;     rv[pos] = v.x;
                  atomicAdd(&g_col_cnt[colbase], 1);     atomicAdd(&g_deg[colbase], v.x);     pos++; }
        if (c1) { ri[pos] = colbase + 1; rv[pos] = v.y;
                  atomicAdd(&g_col_cnt[colbase + 1], 1); atomicAdd(&g_deg[colbase + 1], v.y); pos++; }
        if (c2) { ri[pos] = colbase + 2; rv[pos] = v.z;
                  atomicAdd(&g_col_cnt[colbase + 2], 1); atomicAdd(&g_deg[colbase + 2], v.z); pos++; }
        if (c3) { ri[pos] = colbase + 3; rv[pos] = v.w;
                  atomicAdd(&g_col_cnt[colbase + 3], 1); atomicAdd(&g_deg[colbase + 3], v.w); pos++; }
        base += tot;
        v = vn;
    }
    if (lane == 0) g_row_cnt[warp] = base;
}

__global__ void scan_cols() {
    __shared__ int sm[1024];
    int tid = threadIdx.x;
    int b0 = tid * 5;
    int local[5];
    int s = 0;
#pragma unroll
    for (int j = 0; j < 5; j++) {
        int m = b0 + j;
        int c = (m < MM) ? g_col_cnt[m] : 0;
        local[j] = s; s += c;
    }
    sm[tid] = s;
    __syncthreads();
    for (int off = 1; off < 1024; off <<= 1) {
        int v = (tid >= off) ? sm[tid - off] : 0;
        __syncthreads();
        sm[tid] += v;
        __syncthreads();
    }
    int excl = (tid == 0) ? 0 : sm[tid - 1];
#pragma unroll
    for (int j = 0; j < 5; j++) {
        int m = b0 + j;
        if (m < MM) { g_col_ptr[m] = excl + local[j]; g_col_fill[m] = excl + local[j]; }
    }
    if (tid == 1023) g_col_ptr[MM] = sm[1023];
}

__global__ void __launch_bounds__(256) fill_cols() {
    int warp = (blockIdx.x * blockDim.x + threadIdx.x) >> 5;
    if (warp >= NN) return;
    int lane = threadIdx.x & 31;
    int cnt = g_row_cnt[warp];
    const int* ri = g_row_idx + (size_t)warp * RCAP;
    const float* rv = g_row_val + (size_t)warp * RCAP;
    for (int j = lane; j < cnt; j += 32) {
        int m = ri[j];
        float v = rv[j];
        int p = atomicAdd(&g_col_fill[m], 1);
        g_col_idx[p] = warp;
        g_col_val[p] = v;
    }
}

// ---------------- per-layer kernels ----------------
__global__ void ln_rows(const float* __restrict__ X, float* __restrict__ O,
                        const float* __restrict__ g, const float* __restrict__ b) {
    int warp = (blockIdx.x * blockDim.x + threadIdx.x) >> 5;
    if (warp >= NN) return;
    int lane = threadIdx.x & 31;
    const float4* x4 = (const float4*)(X + (size_t)warp * DD);
    float4 v0 = x4[lane], v1 = x4[lane + 32];
    float s = v0.x + v0.y + v0.z + v0.w + v1.x + v1.y + v1.z + v1.w;
    s = warpSum(s);
    float mean = s * (1.f / 256.f);
    float c0x = v0.x - mean, c0y = v0.y - mean, c0z = v0.z - mean, c0w = v0.w - mean;
    float c1x = v1.x - mean, c1y = v1.y - mean, c1z = v1.z - mean, c1w = v1.w - mean;
    float ss = c0x*c0x + c0y*c0y + c0z*c0z + c0w*c0w + c1x*c1x + c1y*c1y + c1z*c1z + c1w*c1w;
    ss = warpSum(ss);
    float rs = rsqrtf(ss * (1.f / 256.f) + 1e-5f);
    const float4* g4 = (const float4*)g;
    const float4* b4 = (const float4*)b;
    float4 G0 = g4[lane], G1 = g4[lane + 32], B0 = b4[lane], B1 = b4[lane + 32];
    float4* o4 = (float4*)(O + (size_t)warp * DD);
    o4[lane]      = make_float4(c0x*rs*G0.x + B0.x, c0y*rs*G0.y + B0.y,
                                c0z*rs*G0.z + B0.z, c0w*rs*G0.w + B0.w);
    o4[lane + 32] = make_float4(c1x*rs*G1.x + B1.x, c1y*rs*G1.y + B1.y,
                                c1z*rs*G1.z + B1.z, c1w*rs*G1.w + B1.w);
}

__global__ void __launch_bounds__(256) egather_sparse(const float* __restrict__ X,
        const float* __restrict__ g, const float* __restrict__ b) {
    int m = blockIdx.x, d = threadIdx.x;
    int p0 = g_col_ptr[m], p1 = g_col_ptr[m + 1];
    int cnt = p1 - p0;
    __shared__ int sidx[RCAP];
    __shared__ float sval[RCAP];
    __shared__ float sm[8];
    if (d < cnt && d < RCAP) { sidx[d] = g_col_idx[p0 + d]; sval[d] = g_col_val[p0 + d]; }
    __syncthreads();
    float a0 = 0.f, a1 = 0.f, a2 = 0.f, a3 = 0.f;
    int j = 0;
    for (; j + 4 <= cnt; j += 4) {
        int n0 = sidx[j], n1 = sidx[j+1], n2 = sidx[j+2], n3 = sidx[j+3];
        float x0 = X[(size_t)n0 * DD + d], x1 = X[(size_t)n1 * DD + d];
        float x2 = X[(size_t)n2 * DD + d], x3 = X[(size_t)n3 * DD + d];
        a0 = fmaf(sval[j],   x0, a0); a1 = fmaf(sval[j+1], x1, a1);
        a2 = fmaf(sval[j+2], x2, a2); a3 = fmaf(sval[j+3], x3, a3);
    }
    for (; j < cnt; j++) a0 = fmaf(sval[j], X[(size_t)sidx[j] * DD + d], a0);
    float acc = ((a0 + a1) + (a2 + a3)) / g_deg[m];
    float mean = blockSum256(acc, sm) * (1.f / 256.f);
    float c = acc - mean;
    float var = blockSum256(c * c, sm) * (1.f / 256.f);
    float rs = rsqrtf(var + 1e-5f);
    g_En[(size_t)m * DD + d] = c * rs * g[d] + b[d];
}

__global__ void __launch_bounds__(256) egather_dense_part(const float* __restrict__ X) {
    int e = blockIdx.x;          // 0..3
    int slice = blockIdx.y;      // 0..31
    int m = NN + e, d = threadIdx.x;
    int p0 = g_col_ptr[m], p1 = g_col_ptr[m + 1];
    int cnt = p1 - p0;
    int per = (cnt + 31) / 32;
    int s0 = p0 + slice * per;
    int s1 = min(s0 + per, p1);
    float a0 = 0.f, a1 = 0.f, a2 = 0.f, a3 = 0.f;
    int p = s0;
    for (; p + 4 <= s1; p += 4) {
        int n0 = g_col_idx[p], n1 = g_col_idx[p+1], n2 = g_col_idx[p+2], n3 = g_col_idx[p+3];
        float w0 = g_col_val[p], w1 = g_col_val[p+1], w2 = g_col_val[p+2], w3 = g_col_val[p+3];
        a0 = fmaf(w0, X[(size_t)n0 * DD + d], a0);
        a1 = fmaf(w1, X[(size_t)n1 * DD + d], a1);
        a2 = fmaf(w2, X[(size_t)n2 * DD + d], a2);
        a3 = fmaf(w3, X[(size_t)n3 * DD + d], a3);
    }
    for (; p < s1; p++) a0 = fmaf(g_col_val[p], X[(size_t)g_col_idx[p] * DD + d], a0);
    g_epart[(size_t)(e * 32 + slice) * DD + d] = (a0 + a1) + (a2 + a3);
}

__global__ void __launch_bounds__(256) egather_dense_fin(const float* __restrict__ g,
                                                          const float* __restrict__ b) {
    int e = blockIdx.x, d = threadIdx.x;
    float acc = 0.f;
#pragma unroll
    for (int s = 0; s < 32; s++) acc += g_epart[(size_t)(e * 32 + s) * DD + d];
    acc /= g_deg[NN + e];
    __shared__ float sm[8];
    float mean = blockSum256(acc, sm) * (1.f / 256.f);
    float c = acc - mean;
    float var = blockSum256(c * c, sm) * (1.f / 256.f);
    float rs = rsqrtf(var + 1e-5f);
    g_En[(size_t)(NN + e) * DD + d] = c * rs * g[d] + b[d];
}

// ---------------- tf32 tensor-core GEMM (smem-staged) ----------------
// C[rows,256] = A[rows,256] @ W[256,256]^T + bias, fused epilogue.
// Block: 256 threads = 8 warps (4 row-groups x 2 col-groups), 128x64 tile, BK=32.
#define ASTRIDE 40
#define CSTRIDE 68
__device__ __forceinline__ void gemm_tc_body(const float* __restrict__ A,
        const float* __restrict__ W, const float* __restrict__ bias,
        float* __restrict__ C, const float* __restrict__ R, int epi) {
    __shared__ __align__(16) float sm[128 * CSTRIDE];   // 34.8 KB, aliased
    float* As = sm;                    // 128 x ASTRIDE
    float* Ws = sm + 128 * ASTRIDE;    // 64 x ASTRIDE
    int tid = threadIdx.x;
    int wid = tid >> 5;
    int wr = wid >> 1;      // 0..3
    int wc = wid & 1;       // 0..1
    int rowBase = blockIdx.x * 128;
    int colBase = blockIdx.y * 64;

    wmma::fragment<wmma::accumulator, 16, 16, 8, float> acc[2][2];
#pragma unroll
    for (int i = 0; i < 2; i++)
#pragma unroll
        for (int j = 0; j < 2; j++) wmma::fill_fragment(acc[i][j], 0.f);

#pragma unroll 1
    for (int k0 = 0; k0 < 256; k0 += 32) {
        // stage A tile 128x32 (1024 float4, 4/thread)
#pragma unroll
        for (int i = 0; i < 4; i++) {
            int idx = tid + i * 256;
            int row = idx >> 3;
            int c4 = (idx & 7) * 4;
            float4 v = *(const float4*)(A + (size_t)(rowBase + row) * DD + k0 + c4);
            *(float4*)&As[row * ASTRIDE + c4] = v;
        }
        // stage W tile 64x32 (512 float4, 2/thread)
#pragma unroll
        for (int i = 0; i < 2; i++) {
            int idx = tid + i * 256;
            int row = idx >> 3;
            int c4 = (idx & 7) * 4;
            float4 v = *(const float4*)(W + (size_t)(colBase + row) * DD + k0 + c4);
            *(float4*)&Ws[row * ASTRIDE + c4] = v;
        }
        __syncthreads();
#pragma unroll
        for (int kk = 0; kk < 32; kk += 8) {
            wmma::fragment<wmma::matrix_a, 16, 16, 8, wmma::precision::tf32, wmma::row_major> a[2];
            wmma::fragment<wmma::matrix_b, 16, 16, 8, wmma::precision::tf32, wmma::col_major> b[2];
            wmma::load_matrix_sync(a[0], &As[(wr * 32) * ASTRIDE + kk], ASTRIDE);
            wmma::load_matrix_sync(a[1], &As[(wr * 32 + 16) * ASTRIDE + kk], ASTRIDE);
            wmma::load_matrix_sync(b[0], &Ws[(wc * 32) * ASTRIDE + kk], ASTRIDE);
            wmma::load_matrix_sync(b[1], &Ws[(wc * 32 + 16) * ASTRIDE + kk], ASTRIDE);
#pragma unroll
            for (int t = 0; t < a[0].num_elements; t++) {
                a[0].x[t] = wmma::__float_to_tf32(a[0].x[t]);
                a[1].x[t] = wmma::__float_to_tf32(a[1].x[t]);
            }
#pragma unroll
            for (int t = 0; t < b[0].num_elements; t++) {
                b[0].x[t] = wmma::__float_to_tf32(b[0].x[t]);
                b[1].x[t] = wmma::__float_to_tf32(b[1].x[t]);
            }
#pragma unroll
            for (int i = 0; i < 2; i++)
#pragma unroll
                for (int j = 0; j < 2; j++)
                    wmma::mma_sync(acc[i][j], a[i], b[j], acc[i][j]);
        }
        __syncthreads();
    }
    // write accumulators to smem (stride CSTRIDE), then fused epilogue to global
#pragma unroll
    for (int i = 0; i < 2; i++)
#pragma unroll
        for (int j = 0; j < 2; j++)
            wmma::store_matrix_sync(&sm[(wr * 32 + i * 16) * CSTRIDE + wc * 32 + j * 16],
                                    acc[i][j], CSTRIDE, wmma::mem_row_major);
    __syncthreads();

#pragma unroll
    for (int e4 = 0; e4 < 8; e4++) {
        int linear = tid + e4 * 256;      // 0..2047 float4 slots
        int row = linear >> 4;            // 16 float4 per 64-wide row
        int col = (linear & 15) * 4;
        float4 v = *(float4*)&sm[row * CSTRIDE + col];
        float4 bv = *(const float4*)(bias + colBase + col);
        v.x += bv.x; v.y += bv.y; v.z += bv.z; v.w += bv.w;
        int grow = rowBase + row;
        if (epi == 1) {
            float4 rv = *(const float4*)(R + (size_t)grow * DD + colBase + col);
            v.x = fmaxf(v.x, 0.f) * 0.5f + 0.5f * rv.x;
            v.y = fmaxf(v.y, 0.f) * 0.5f + 0.5f * rv.y;
            v.z = fmaxf(v.z, 0.f) * 0.5f + 0.5f * rv.z;
            v.w = fmaxf(v.w, 0.f) * 0.5f + 0.5f * rv.w;
        } else if (epi == 2) {
            v.x = tanhf(v.x); v.y = tanhf(v.y); v.z = tanhf(v.z); v.w = tanhf(v.w);
        } else if (epi == 3) {
            v.x = 1.f / (1.f + __expf(-v.x)); v.y = 1.f / (1.f + __expf(-v.y));
            v.z = 1.f / (1.f + __expf(-v.z)); v.w = 1.f / (1.f + __expf(-v.w));
        }
        *(float4*)(C + (size_t)grow * DD + colBase + col) = v;
    }
}

template <int EPI>
__global__ void __launch_bounds__(256) gemm_tc(const float* __restrict__ A,
        const float* __restrict__ W, const float* __restrict__ bias,
        float* __restrict__ C, const float* __restrict__ R) {
    gemm_tc_body(A, W, bias, C, R, EPI);
}

template <int EPI0, int EPI1>
__global__ void __launch_bounds__(256) gemm_tc_dual(
        const float* __restrict__ A0, const float* __restrict__ W0,
        const float* __restrict__ b0, float* __restrict__ C0,
        const float* __restrict__ A1, const float* __restrict__ W1,
        const float* __restrict__ b1, float* __restrict__ C1) {
    if (blockIdx.z == 0) gemm_tc_body(A0, W0, b0, C0, nullptr, EPI0);
    else                 gemm_tc_body(A1, W1, b1, C1, nullptr, EPI1);
}

// tail k rows: parallel over 32 blocks (256 warps, 4 outputs each)
__global__ void __launch_bounds__(256) ktail_par(
        const float* __restrict__ Wkt, const float* __restrict__ bkt,
        const float* __restrict__ Wks, const float* __restrict__ bks) {
    __shared__ __align__(16) float e[4][DD];
    int tid = threadIdx.x;
#pragma unroll
    for (int r = 0; r < 4; r++) e[r][tid] = g_En[(size_t)(NN + r) * DD + tid];
    __syncthreads();
    int w = tid >> 5, lane = tid & 31;
    int gw = blockIdx.x * 8 + w;   // 0..255
    for (int t = gw; t < 4 * DD; t += 256) {
        int r = t >> 8, o = t & 255;
        const float* wrow = ((r < 3) ? Wkt : Wks) + (size_t)o * DD;
        const float4* w4 = (const float4*)wrow;
        const float4* e4 = (const float4*)e[r];
        float4 a = w4[lane], b = e4[lane];
        float acc = a.x*b.x + a.y*b.y + a.z*b.z + a.w*b.w;
        float4 a2 = w4[lane + 32], b2 = e4[lane + 32];
        acc += a2.x*b2.x + a2.y*b2.y + a2.z*b2.z + a2.w*b2.w;
        acc = warpSum(acc);
        if (lane == 0) g_k[(size_t)(NN + r) * DD + o] = acc + ((r < 3) ? bkt[o] : bks[o]);
    }
}

// sparse masked MHA, single pass online softmax; block per node, warp per head.
__global__ void __launch_bounds__(256) attn_k() {
    int n = blockIdx.x;
    int tid = threadIdx.x;
    int h = tid >> 5, lane = tid & 31;
    __shared__ int sidx[RCAP];
    int cnt = g_row_cnt[n];
    if (tid < cnt) sidx[tid] = g_row_idx[(size_t)n * RCAP + tid];
    __syncthreads();
    int off = h * 32 + lane;
    float qv = g_q[(size_t)n * DD + off];
    float m = -1e30f, s = 0.f, acc = 0.f;
    const float sc = 0.17677669529663687f;  // 1/sqrt(32)
    for (int j0 = 0; j0 < cnt; j0 += 4) {
        int c = cnt - j0;
        float kv0 = g_k[(size_t)sidx[j0] * DD + off];
        float kv1 = (c > 1) ? g_k[(size_t)sidx[j0+1] * DD + off] : 0.f;
        float kv2 = (c > 2) ? g_k[(size_t)sidx[j0+2] * DD + off] : 0.f;
        float kv3 = (c > 3) ? g_k[(size_t)sidx[j0+3] * DD + off] : 0.f;
        float p0 = qv * kv0, p1 = qv * kv1, p2 = qv * kv2, p3 = qv * kv3;
#pragma unroll
        for (int o = 16; o; o >>= 1) {
            p0 += __shfl_xor_sync(0xffffffffu, p0, o);
            p1 += __shfl_xor_sync(0xffffffffu, p1, o);
            p2 += __shfl_xor_sync(0xffffffffu, p2, o);
            p3 += __shfl_xor_sync(0xffffffffu, p3, o);
        }
        p0 *= sc; p1 *= sc; p2 *= sc; p3 *= sc;
        {
            if (p0 > m) { float r = __expf(m - p0); s *= r; acc *= r; m = p0; }
            float e = __expf(p0 - m); s += e; acc = fmaf(e, kv0, acc);
        }
        if (c > 1) {
            if (p1 > m) { float r = __expf(m - p1); s *= r; acc *= r; m = p1; }
            float e = __expf(p1 - m); s += e; acc = fmaf(e, kv1, acc);
        }
        if (c > 2) {
            if (p2 > m) { float r = __expf(m - p2); s *= r; acc *= r; m = p2; }
            float e = __expf(p2 - m); s += e; acc = fmaf(e, kv2, acc);
        }
        if (c > 3) {
            if (p3 > m) { float r = __expf(m - p3); s *= r; acc *= r; m = p3; }
            float e = __expf(p3 - m); s += e; acc = fmaf(e, kv3, acc);
        }
    }
    g_af[(size_t)n * DD + off] = acc / s;
}

// ---------------- pooling head ----------------
__global__ void gated_score(const float* __restrict__ cw, const float* __restrict__ cb) {
    int warp = (blockIdx.x * blockDim.x + threadIdx.x) >> 5;
    if (warp >= NN) return;
    int lane = threadIdx.x & 31;
    const float4* a4 = (const float4*)(g_ga + (size_t)warp * DD);
    const float4* b4 = (const float4*)(g_gb + (size_t)warp * DD);
    const float4* c4 = (const float4*)cw;
    float acc = 0.f;
#pragma unroll
    for (int t = 0; t < 2; t++) {
        float4 a = a4[lane + t * 32], b = b4[lane + t * 32], c = c4[lane + t * 32];
        acc += a.x*b.x*c.x + a.y*b.y*c.y + a.z*b.z*c.z + a.w*b.w*c.w;
    }
    acc = warpSum(acc);
    if (lane == 0) g_A[warp] = acc + cb[0];
}

__global__ void softmax_stats() {
    __shared__ float sm[32];
    int tid = threadIdx.x, lane = tid & 31, w = tid >> 5;
    float mx = -1e30f;
    for (int i = tid; i < NN; i += 1024) mx = fmaxf(mx, g_A[i]);
    mx = warpMax(mx);
    if (lane == 0) sm[w] = mx;
    __syncthreads();
    if (w == 0) { float v = sm[lane]; v = warpMax(v); if (lane == 0) sm[0] = v; }
    __syncthreads();
    mx = sm[0];
    __syncthreads();
    float s = 0.f;
    for (int i = tid; i < NN; i += 1024) s += __expf(g_A[i] - mx);
    s = warpSum(s);
    if (lane == 0) sm[w] = s;
    __syncthreads();
    if (tid == 0) {
        float t = 0.f;
        for (int i = 0; i < 32; i++) t += sm[i];
        g_red[0] = mx; g_red[1] = t;
    }
}

__global__ void pool_partial(const float* __restrict__ F) {
    int d = threadIdx.x, b = blockIdx.x;
    float mx = g_red[0];
    float acc = 0.f;
    int n0 = b * 64;
    for (int j = 0; j < 64; j++) {
        float wgt = __expf(g_A[n0 + j] - mx);
        acc = fmaf(wgt, F[(size_t)(n0 + j) * DD + d], acc);
    }
    g_part[b * DD + d] = acc;
}

__global__ void final_out(const float* __restrict__ ow, const float* __restrict__ ob,
                          float* __restrict__ out) {
    __shared__ float pooled[DD];
    int d = threadIdx.x;
    float acc = 0.f;
    for (int b = 0; b < 64; b++) acc += g_part[b * DD + d];
    pooled[d] = acc / g_red[1];
    __syncthreads();
    int h = d >> 5, lane = d & 31;
    if (h < 4) {
        const float* w = ow + (size_t)h * DD;
        float a = 0.f;
        for (int k = lane; k < DD; k += 32) a = fmaf(pooled[k], w[k], a);
        a = warpSum(a);
        if (lane == 0) out[h] = a + ob[h];
    }
}

// ---------------- host orchestration ----------------
struct DevPtrs {
    float *Xn, *En, *q, *k, *af, *X1, *X2, *ga, *gb;
};

static DevPtrs get_ptrs() {
    static DevPtrs p = {};
    static bool init = false;
    if (!init) {
        cudaGetSymbolAddress((void**)&p.Xn, g_Xn);
        cudaGetSymbolAddress((void**)&p.En, g_En);
        cudaGetSymbolAddress((void**)&p.q,  g_q);
        cudaGetSymbolAddress((void**)&p.k,  g_k);
        cudaGetSymbolAddress((void**)&p.af, g_af);
        cudaGetSymbolAddress((void**)&p.X1, g_X1);
        cudaGetSymbolAddress((void**)&p.X2, g_X2);
        cudaGetSymbolAddress((void**)&p.ga, g_ga);
        cudaGetSymbolAddress((void**)&p.gb, g_gb);
        init = true;
    }
    return p;
}

static void run_layer(const DevPtrs& p, const float* Xin, float* Xout, int l,
                      const float* Wq_w, const float* Wq_b,
                      const float* Wkn_w, const float* Wkn_b,
                      const float* Wkt_w, const float* Wkt_b,
                      const float* Wks_w, const float* Wks_b,
                      const float* fc_w, const float* fc_b,
                      const float* ln_g, const float* ln_b) {
    const int WOFF = DD * DD;
    ln_rows<<<512, 256>>>(Xin, p.Xn, ln_g + l * DD, ln_b + l * DD);
    egather_sparse<<<NN, 256>>>(Xin, ln_g + l * DD, ln_b + l * DD);
    egather_dense_part<<<dim3(4, 32), 256>>>(Xin);
    egather_dense_fin<<<4, 256>>>(ln_g + l * DD, ln_b + l * DD);
    dim3 grid2(32, 4, 2);
    gemm_tc_dual<0, 0><<<grid2, 256>>>(p.Xn, Wq_w + l * WOFF, Wq_b + l * DD, p.q,
                                       p.En, Wkn_w + l * WOFF, Wkn_b + l * DD, p.k);
    ktail_par<<<32, 256>>>(Wkt_w + l * WOFF, Wkt_b + l * DD,
                           Wks_w + l * WOFF, Wks_b + l * DD);
    attn_k<<<NN, 256>>>();
    dim3 grid(32, 4);
    gemm_tc<1><<<grid, 256>>>(p.af, fc_w + l * WOFF, fc_b + l * DD, Xout, Xin);
}

extern "C" void kernel_launch(void* const* d_in, const int* in_sizes, int n_in,
                              void* d_out, int out_size) {
    (void)in_sizes; (void)n_in; (void)out_size;
    const float* X     = (const float*)d_in[0];
    const float* H     = (const float*)d_in[1];
    const float* Wq_w  = (const float*)d_in[2];
    const float* Wq_b  = (const float*)d_in[3];
    const float* Wkn_w = (const float*)d_in[4];
    const float* Wkn_b = (const float*)d_in[5];
    const float* Wkt_w = (const float*)d_in[6];
    const float* Wkt_b = (const float*)d_in[7];
    const float* Wks_w = (const float*)d_in[8];
    const float* Wks_b = (const float*)d_in[9];
    const float* fc_w  = (const float*)d_in[10];
    const float* fc_b  = (const float*)d_in[11];
    const float* ln_g  = (const float*)d_in[12];
    const float* ln_b  = (const float*)d_in[13];
    const float* aw    = (const float*)d_in[14];
    const float* ab    = (const float*)d_in[15];
    const float* bw    = (const float*)d_in[16];
    const float* bb    = (const float*)d_in[17];
    const float* cw    = (const float*)d_in[18];
    const float* cb    = (const float*)d_in[19];
    const float* out_w = (const float*)d_in[20];
    const float* out_b = (const float*)d_in[21];
    float* out = (float*)d_out;

    DevPtrs p = get_ptrs();

    // structure build from H (single pass over H)
    init_k<<<32, 256>>>();
    build_rows<<<512, 256>>>(H);
    scan_cols<<<1, 1024>>>();
    fill_cols<<<512, 256>>>();

    // two HetHyper layers
    run_layer(p, X,    p.X1, 0, Wq_w, Wq_b, Wkn_w, Wkn_b, Wkt_w, Wkt_b,
              Wks_w, Wks_b, fc_w, fc_b, ln_g, ln_b);
    run_layer(p, p.X1, p.X2, 1, Wq_w, Wq_b, Wkn_w, Wkn_b, Wkt_w, Wkt_b,
              Wks_w, Wks_b, fc_w, fc_b, ln_g, ln_b);

    // gated attention pooling + classifier
    dim3 grid2(32, 4, 2);
    gemm_tc_dual<2, 3><<<grid2, 256>>>(p.X2, aw, ab, p.ga, p.X2, bw, bb, p.gb);
    gated_score<<<512, 256>>>(cw, cb);
    softmax_stats<<<1, 1024>>>();
    pool_partial<<<64, 256>>>(p.X2);
    final_out<<<1, 256>>>(out_w, out_b, out);
}